// round 5
// baseline (speedup 1.0000x reference)
#include <cuda_runtime.h>
#include <cuda_fp16.h>
#include <cstdint>
#include <math.h>

// Problem constants
#define T_TOK 4096
#define D_MODEL 1024
#define D_MLP 3584
#define NEXP 8

// GEMM tile config
#define BM 128
#define BN 64
#define BK 64
#define THREADS 256
#define NSTAGE 3

// smem stage sizes (bytes)
#define A_BYTES (BM * BK * 2)             // 16384
#define B_BYTES (BN * BK * 2)             // 8192
#define STAGE1 (A_BYTES + 2 * B_BYTES)    // 32768 (gemm1: A + B1 + B3)
#define STAGE2 (A_BYTES + B_BYTES)        // 24576 (gemm2: A + B)

// ---------------- device scratch (static: no cudaMalloc allowed) ----------------
static __device__ __align__(16) __half g_xh[T_TOK * D_MODEL];
static __device__ __align__(16) __half g_w1h[NEXP * D_MLP * D_MODEL];
static __device__ __align__(16) __half g_w3h[NEXP * D_MLP * D_MODEL];
static __device__ __align__(16) __half g_w2h[NEXP * D_MODEL * D_MLP];
static __device__ __align__(16) __half g_h[(size_t)NEXP * T_TOK * D_MLP];
static __device__ __align__(16) float  g_scr[(size_t)NEXP * T_TOK * D_MODEL]; // expert outputs
static __device__ int    g_cnt[NEXP];
static __device__ int    g_list[NEXP * T_TOK];
static __device__ int    g_slot0[T_TOK];
static __device__ int    g_slot1[T_TOK];
static __device__ float  g_cw0[T_TOK];
static __device__ float  g_cw1[T_TOK];

// ---------------- helpers ----------------
__device__ __forceinline__ void mma16816(float* c, const uint32_t* a, const uint32_t* b) {
    asm volatile(
        "mma.sync.aligned.m16n8k16.row.col.f32.f16.f16.f32 "
        "{%0,%1,%2,%3}, {%4,%5,%6,%7}, {%8,%9}, {%0,%1,%2,%3};"
        : "+f"(c[0]), "+f"(c[1]), "+f"(c[2]), "+f"(c[3])
        : "r"(a[0]), "r"(a[1]), "r"(a[2]), "r"(a[3]), "r"(b[0]), "r"(b[1]));
}

__device__ __forceinline__ void ldsm4(uint32_t* r, uint32_t saddr) {
    asm volatile("ldmatrix.sync.aligned.m8n8.x4.shared.b16 {%0,%1,%2,%3}, [%4];"
                 : "=r"(r[0]), "=r"(r[1]), "=r"(r[2]), "=r"(r[3]) : "r"(saddr));
}

__device__ __forceinline__ void cp16(uint32_t dst, const void* src) {
    asm volatile("cp.async.cg.shared.global [%0], [%1], 16;" :: "r"(dst), "l"(src));
}
#define CP_COMMIT() asm volatile("cp.async.commit_group;")
#define CP_WAIT1()  asm volatile("cp.async.wait_group 1;")
#define CP_WAIT0()  asm volatile("cp.async.wait_group 0;")

__device__ __forceinline__ uint32_t smem_u32(const void* p) {
    return (uint32_t)__cvta_generic_to_shared(p);
}

// ---------------- kernel 0: zero expert counters ----------------
__global__ void zero_kernel() {
    if (threadIdx.x < NEXP) g_cnt[threadIdx.x] = 0;
}

// ---------------- weight fp32 -> fp16 (dst selected device-side) ----------------
__global__ void cvt_w_kernel(const float* __restrict__ w1,
                             const float* __restrict__ w3,
                             const float* __restrict__ w2) {
    const int n4 = (NEXP * D_MLP * D_MODEL) / 4;
    const float* src;
    __half* dst;
    if (blockIdx.y == 0)      { src = w1; dst = g_w1h; }
    else if (blockIdx.y == 1) { src = w3; dst = g_w3h; }
    else                      { src = w2; dst = g_w2h; }
    const float4* s4 = reinterpret_cast<const float4*>(src);
    __half2* d2 = reinterpret_cast<__half2*>(dst);
    int i = blockIdx.x * blockDim.x + threadIdx.x;
    for (; i < n4; i += gridDim.x * blockDim.x) {
        float4 v = s4[i];
        d2[2 * i + 0] = __floats2half2_rn(v.x, v.y);
        d2[2 * i + 1] = __floats2half2_rn(v.z, v.w);
    }
}

// ---------------- gating (warp per token) + x->fp16 + slot map ----------------
__global__ void gate_kernel(const float* __restrict__ x, const float* __restrict__ wg) {
    int t = blockIdx.x * 4 + (threadIdx.x >> 5);
    int lane = threadIdx.x & 31;
    if (t >= T_TOK) return;
    const float* xr = x + (size_t)t * D_MODEL;
    float acc[NEXP];
#pragma unroll
    for (int e = 0; e < NEXP; e++) acc[e] = 0.f;
    for (int d = lane; d < D_MODEL; d += 32) {
        float xv = xr[d];
        g_xh[(size_t)t * D_MODEL + d] = __float2half_rn(xv);
#pragma unroll
        for (int e = 0; e < NEXP; e++) acc[e] += xv * wg[e * D_MODEL + d];
    }
#pragma unroll
    for (int e = 0; e < NEXP; e++)
#pragma unroll
        for (int o = 16; o; o >>= 1) acc[e] += __shfl_xor_sync(0xFFFFFFFFu, acc[e], o);
    if (lane == 0) {
        int i0 = 0;
        float l0 = acc[0];
#pragma unroll
        for (int e = 1; e < NEXP; e++)
            if (acc[e] > l0) { l0 = acc[e]; i0 = e; }
        int i1 = -1;
        float l1 = -INFINITY;
#pragma unroll
        for (int e = 0; e < NEXP; e++)
            if (e != i0 && acc[e] > l1) { l1 = acc[e]; i1 = e; }
        float e1 = expf(l1 - l0);
        float s = 1.f + e1;
        float w0 = 1.f / s, w1 = e1 / s;
        int p0 = atomicAdd(&g_cnt[i0], 1);
        g_list[i0 * T_TOK + p0] = t;
        int p1 = atomicAdd(&g_cnt[i1], 1);
        g_list[i1 * T_TOK + p1] = t;
        g_slot0[t] = i0 * T_TOK + p0;
        g_slot1[t] = i1 * T_TOK + p1;
        g_cw0[t] = w0;
        g_cw1[t] = w1;
    }
}

// ---------------- grouped GEMM1: h = silu(X@W1^T) * (X@W3^T), fp16 out ----------------
// grid: (D_MLP/BN, T_TOK/BM, NEXP), block 256, dynamic smem NSTAGE*STAGE1
__global__ void __launch_bounds__(THREADS, 2) gemm1_kernel() {
    int e = blockIdx.z, mt = blockIdx.y, nt = blockIdx.x;
    int cnt = g_cnt[e];
    if (mt * BM >= cnt) return;

    extern __shared__ __align__(128) char sm1[];
    uint32_t sbase = smem_u32(sm1);

    int tid = threadIdx.x, lane = tid & 31, warp = tid >> 5;
    int wm = warp & 3, wn = warp >> 2;       // 4 x 2 warp grid
    int g = lane >> 2, tg = lane & 3;
    int l15 = lane & 15, hi = lane >> 4;

    // ---- global->smem load setup (16B chunks, 8 per 128B row) ----
    const __half* asrc[4]; uint32_t adst[4];
#pragma unroll
    for (int i = 0; i < 4; i++) {
        int lin = i * THREADS + tid;          // 1024 chunks over 128 rows
        int row = lin >> 3, ch = lin & 7;
        int s = mt * BM + row;
        int tok = g_list[e * T_TOK + min(s, cnt - 1)];
        asrc[i] = g_xh + (size_t)tok * D_MODEL + ch * 8;
        adst[i] = sbase + row * 128 + ((uint32_t)(ch ^ (row & 7)) << 4);
    }
    const __half* b1src[2]; const __half* b3src[2]; uint32_t bdst[2];
#pragma unroll
    for (int i = 0; i < 2; i++) {
        int lin = i * THREADS + tid;          // 512 chunks over 64 rows
        int row = lin >> 3, ch = lin & 7;
        size_t off = ((size_t)e * D_MLP + nt * BN + row) * D_MODEL + ch * 8;
        b1src[i] = g_w1h + off;
        b3src[i] = g_w3h + off;
        bdst[i] = sbase + A_BYTES + row * 128 + ((uint32_t)(ch ^ (row & 7)) << 4);
    }

    // ---- ldmatrix address precompute ----
    uint32_t aA[2]; int xA[2];
#pragma unroll
    for (int tm = 0; tm < 2; tm++) {
        int r = wm * 32 + tm * 16 + l15;
        aA[tm] = sbase + r * 128;
        xA[tm] = r & 7;
    }
    uint32_t aB[2]; int xB[2];
#pragma unroll
    for (int ns = 0; ns < 2; ns++) {
        int r = wn * 32 + ns * 16 + l15;
        aB[ns] = sbase + A_BYTES + r * 128;
        xB[ns] = r & 7;
    }

    float c1[2][4][4] = {}, c3[2][4][4] = {};

    const int NK = D_MODEL / BK;  // 16

    auto fill = [&](int st, int kc) {
        uint32_t so = (uint32_t)st * STAGE1;
        int ko = kc * BK;
#pragma unroll
        for (int i = 0; i < 4; i++) cp16(adst[i] + so, asrc[i] + ko);
#pragma unroll
        for (int i = 0; i < 2; i++) {
            cp16(bdst[i] + so, b1src[i] + ko);
            cp16(bdst[i] + so + B_BYTES, b3src[i] + ko);
        }
        CP_COMMIT();
    };

    // prologue: stages 0,1
    fill(0, 0);
    fill(1, 1);

    for (int kt = 0; kt < NK; kt++) {
        if (kt < NK - 1) { CP_WAIT1(); } else { CP_WAIT0(); }
        __syncthreads();
        if (kt + 2 < NK) fill((kt + 2) % NSTAGE, kt + 2);
        uint32_t so = (uint32_t)(kt % NSTAGE) * STAGE1;
#pragma unroll
        for (int kk = 0; kk < 4; kk++) {
            uint32_t a[2][4], q1[2][4], q3[2][4];
#pragma unroll
            for (int tm = 0; tm < 2; tm++)
                ldsm4(a[tm], aA[tm] + so + ((uint32_t)((kk * 2 + hi) ^ xA[tm]) << 4));
#pragma unroll
            for (int ns = 0; ns < 2; ns++) {
                uint32_t sw = (uint32_t)((kk * 2 + hi) ^ xB[ns]) << 4;
                ldsm4(q1[ns], aB[ns] + so + sw);
                ldsm4(q3[ns], aB[ns] + so + sw + B_BYTES);
            }
#pragma unroll
            for (int tm = 0; tm < 2; tm++)
#pragma unroll
                for (int ns = 0; ns < 2; ns++) {
                    uint32_t b1a[2] = {q1[ns][0], q1[ns][2]}, b1b[2] = {q1[ns][1], q1[ns][3]};
                    uint32_t b3a[2] = {q3[ns][0], q3[ns][2]}, b3b[2] = {q3[ns][1], q3[ns][3]};
                    mma16816(c1[tm][ns * 2 + 0], a[tm], b1a);
                    mma16816(c1[tm][ns * 2 + 1], a[tm], b1b);
                    mma16816(c3[tm][ns * 2 + 0], a[tm], b3a);
                    mma16816(c3[tm][ns * 2 + 1], a[tm], b3b);
                }
        }
    }

    // epilogue: h = silu(h1) * h3 -> fp16
#pragma unroll
    for (int tm = 0; tm < 2; tm++)
#pragma unroll
        for (int pair = 0; pair < 2; pair++) {
            int s = mt * BM + wm * 32 + tm * 16 + g + pair * 8;
            if (s >= cnt) continue;
#pragma unroll
            for (int tn = 0; tn < 4; tn++) {
                float h1a = c1[tm][tn][pair * 2 + 0];
                float h1b = c1[tm][tn][pair * 2 + 1];
                float h3a = c3[tm][tn][pair * 2 + 0];
                float h3b = c3[tm][tn][pair * 2 + 1];
                float ha = h1a / (1.f + expf(-h1a)) * h3a;
                float hb = h1b / (1.f + expf(-h1b)) * h3b;
                int col = nt * BN + wn * 32 + tn * 8 + tg * 2;
                *reinterpret_cast<__half2*>(&g_h[((size_t)e * T_TOK + s) * D_MLP + col]) =
                    __floats2half2_rn(ha, hb);
            }
        }
}

// ---------------- grouped GEMM2: scr[slot] = H @ W2^T (no atomics) ----------------
// grid: (D_MODEL/BN, T_TOK/BM, NEXP), block 256, dynamic smem NSTAGE*STAGE2
__global__ void __launch_bounds__(THREADS, 2) gemm2_kernel() {
    int e = blockIdx.z, mt = blockIdx.y, nt = blockIdx.x;
    int cnt = g_cnt[e];
    if (mt * BM >= cnt) return;

    extern __shared__ __align__(128) char sm2[];
    uint32_t sbase = smem_u32(sm2);

    int tid = threadIdx.x, lane = tid & 31, warp = tid >> 5;
    int wm = warp & 3, wn = warp >> 2;
    int g = lane >> 2, tg = lane & 3;
    int l15 = lane & 15, hi = lane >> 4;

    const __half* asrc[4]; uint32_t adst[4];
#pragma unroll
    for (int i = 0; i < 4; i++) {
        int lin = i * THREADS + tid;
        int row = lin >> 3, ch = lin & 7;
        asrc[i] = g_h + ((size_t)e * T_TOK + mt * BM + row) * D_MLP + ch * 8;
        adst[i] = sbase + row * 128 + ((uint32_t)(ch ^ (row & 7)) << 4);
    }
    const __half* bsrc[2]; uint32_t bdst[2];
#pragma unroll
    for (int i = 0; i < 2; i++) {
        int lin = i * THREADS + tid;
        int row = lin >> 3, ch = lin & 7;
        bsrc[i] = g_w2h + ((size_t)e * D_MODEL + nt * BN + row) * D_MLP + ch * 8;
        bdst[i] = sbase + A_BYTES + row * 128 + ((uint32_t)(ch ^ (row & 7)) << 4);
    }

    uint32_t aA[2]; int xA[2];
#pragma unroll
    for (int tm = 0; tm < 2; tm++) {
        int r = wm * 32 + tm * 16 + l15;
        aA[tm] = sbase + r * 128;
        xA[tm] = r & 7;
    }
    uint32_t aB[2]; int xB[2];
#pragma unroll
    for (int ns = 0; ns < 2; ns++) {
        int r = wn * 32 + ns * 16 + l15;
        aB[ns] = sbase + A_BYTES + r * 128;
        xB[ns] = r & 7;
    }

    float c[2][4][4] = {};

    const int NK = D_MLP / BK;  // 56

    auto fill = [&](int st, int kc) {
        uint32_t so = (uint32_t)st * STAGE2;
        int ko = kc * BK;
#pragma unroll
        for (int i = 0; i < 4; i++) cp16(adst[i] + so, asrc[i] + ko);
#pragma unroll
        for (int i = 0; i < 2; i++) cp16(bdst[i] + so, bsrc[i] + ko);
        CP_COMMIT();
    };

    fill(0, 0);
    fill(1, 1);

    for (int kt = 0; kt < NK; kt++) {
        if (kt < NK - 1) { CP_WAIT1(); } else { CP_WAIT0(); }
        __syncthreads();
        if (kt + 2 < NK) fill((kt + 2) % NSTAGE, kt + 2);
        uint32_t so = (uint32_t)(kt % NSTAGE) * STAGE2;
#pragma unroll
        for (int kk = 0; kk < 4; kk++) {
            uint32_t a[2][4], q[2][4];
#pragma unroll
            for (int tm = 0; tm < 2; tm++)
                ldsm4(a[tm], aA[tm] + so + ((uint32_t)((kk * 2 + hi) ^ xA[tm]) << 4));
#pragma unroll
            for (int ns = 0; ns < 2; ns++)
                ldsm4(q[ns], aB[ns] + so + ((uint32_t)((kk * 2 + hi) ^ xB[ns]) << 4));
#pragma unroll
            for (int tm = 0; tm < 2; tm++)
#pragma unroll
                for (int ns = 0; ns < 2; ns++) {
                    uint32_t ba[2] = {q[ns][0], q[ns][2]}, bb[2] = {q[ns][1], q[ns][3]};
                    mma16816(c[tm][ns * 2 + 0], a[tm], ba);
                    mma16816(c[tm][ns * 2 + 1], a[tm], bb);
                }
        }
    }

    // epilogue: plain stores to per-slot scratch (combine kernel applies gate weights)
#pragma unroll
    for (int tm = 0; tm < 2; tm++)
#pragma unroll
        for (int pair = 0; pair < 2; pair++) {
            int s = mt * BM + wm * 32 + tm * 16 + g + pair * 8;
            if (s >= cnt) continue;
            float* dst = g_scr + ((size_t)e * T_TOK + s) * D_MODEL;
#pragma unroll
            for (int tn = 0; tn < 4; tn++) {
                int col = nt * BN + wn * 32 + tn * 8 + tg * 2;
                float2 v = make_float2(c[tm][tn][pair * 2 + 0], c[tm][tn][pair * 2 + 1]);
                *reinterpret_cast<float2*>(dst + col) = v;
            }
        }
}

// ---------------- combine: out[t] = w0*scr[slot0] + w1*scr[slot1] ----------------
// grid: T_TOK blocks x 256 threads (one float4 each)
__global__ void combine_kernel(float* __restrict__ out) {
    int t = blockIdx.x;
    int d4 = threadIdx.x;
    int s0 = g_slot0[t], s1 = g_slot1[t];
    float w0 = g_cw0[t], w1 = g_cw1[t];
    const float4* a = reinterpret_cast<const float4*>(g_scr + (size_t)s0 * D_MODEL);
    const float4* b = reinterpret_cast<const float4*>(g_scr + (size_t)s1 * D_MODEL);
    float4 va = a[d4], vb = b[d4];
    float4 r;
    r.x = w0 * va.x + w1 * vb.x;
    r.y = w0 * va.y + w1 * vb.y;
    r.z = w0 * va.z + w1 * vb.z;
    r.w = w0 * va.w + w1 * vb.w;
    reinterpret_cast<float4*>(out + (size_t)t * D_MODEL)[d4] = r;
}

// ---------------- launch ----------------
extern "C" void kernel_launch(void* const* d_in, const int* in_sizes, int n_in,
                              void* d_out, int out_size) {
    const float* x = (const float*)d_in[0];
    const float* w_gate = (const float*)d_in[1];
    const float* w1 = (const float*)d_in[2];
    const float* w3 = (const float*)d_in[3];
    const float* w2 = (const float*)d_in[4];
    float* out = (float*)d_out;

    cudaFuncSetAttribute(gemm1_kernel, cudaFuncAttributeMaxDynamicSharedMemorySize, NSTAGE * STAGE1);
    cudaFuncSetAttribute(gemm2_kernel, cudaFuncAttributeMaxDynamicSharedMemorySize, NSTAGE * STAGE2);

    // 1. zero expert counters
    zero_kernel<<<1, 32>>>();

    // 2. weight conversion fp32 -> fp16
    dim3 gcvt(2048, 3);
    cvt_w_kernel<<<gcvt, 256>>>(w1, w3, w2);

    // 3. gating + x conversion
    gate_kernel<<<T_TOK / 4, 128>>>(x, w_gate);

    // 4. grouped GEMM1 + SwiGLU
    dim3 g1(D_MLP / BN, T_TOK / BM, NEXP);
    gemm1_kernel<<<g1, THREADS, NSTAGE * STAGE1>>>();

    // 5. grouped GEMM2 -> scratch
    dim3 g2(D_MODEL / BN, T_TOK / BM, NEXP);
    gemm2_kernel<<<g2, THREADS, NSTAGE * STAGE2>>>();

    // 6. weighted combine
    combine_kernel<<<T_TOK, 256>>>(out);
}

// round 6
// speedup vs baseline: 1.0318x; 1.0318x over previous
#include <cuda_runtime.h>
#include <cuda_fp16.h>
#include <cstdint>
#include <math.h>

// Problem constants
#define T_TOK 4096
#define D_MODEL 1024
#define D_MLP 3584
#define NEXP 8

// GEMM tile config
#define BM 128
#define BN 64
#define BK 64
#define THREADS 256
#define NS1 3            // gemm1 pipeline stages
#define NS2 4            // gemm2 pipeline stages

// smem stage sizes (bytes)
#define A_BYTES (BM * BK * 2)             // 16384
#define B_BYTES (BN * BK * 2)             // 8192
#define STAGE1 (A_BYTES + 2 * B_BYTES)    // 32768 (gemm1: A + B1 + B3)
#define STAGE2 (A_BYTES + B_BYTES)        // 24576 (gemm2: A + B)

// ---------------- device scratch (static: no cudaMalloc allowed) ----------------
static __device__ __align__(16) __half g_xh[T_TOK * D_MODEL];
static __device__ __align__(16) __half g_w1h[NEXP * D_MLP * D_MODEL];
static __device__ __align__(16) __half g_w3h[NEXP * D_MLP * D_MODEL];
static __device__ __align__(16) __half g_w2h[NEXP * D_MODEL * D_MLP];
static __device__ __align__(16) __half g_h[(size_t)NEXP * T_TOK * D_MLP];
static __device__ __align__(16) float  g_scr[(size_t)NEXP * T_TOK * D_MODEL];
static __device__ int    g_cnt[NEXP];
static __device__ int    g_list[NEXP * T_TOK];
static __device__ int    g_slot0[T_TOK];
static __device__ int    g_slot1[T_TOK];
static __device__ float  g_cw0[T_TOK];
static __device__ float  g_cw1[T_TOK];

// ---------------- helpers ----------------
__device__ __forceinline__ void mma16816(float* c, const uint32_t* a, const uint32_t* b) {
    asm volatile(
        "mma.sync.aligned.m16n8k16.row.col.f32.f16.f16.f32 "
        "{%0,%1,%2,%3}, {%4,%5,%6,%7}, {%8,%9}, {%0,%1,%2,%3};"
        : "+f"(c[0]), "+f"(c[1]), "+f"(c[2]), "+f"(c[3])
        : "r"(a[0]), "r"(a[1]), "r"(a[2]), "r"(a[3]), "r"(b[0]), "r"(b[1]));
}

__device__ __forceinline__ void ldsm4(uint32_t* r, uint32_t saddr) {
    asm volatile("ldmatrix.sync.aligned.m8n8.x4.shared.b16 {%0,%1,%2,%3}, [%4];"
                 : "=r"(r[0]), "=r"(r[1]), "=r"(r[2]), "=r"(r[3]) : "r"(saddr));
}

__device__ __forceinline__ void cp16(uint32_t dst, const void* src) {
    asm volatile("cp.async.cg.shared.global [%0], [%1], 16;" :: "r"(dst), "l"(src));
}
#define CP_COMMIT() asm volatile("cp.async.commit_group;")
#define CP_WAIT2()  asm volatile("cp.async.wait_group 2;")
#define CP_WAIT1()  asm volatile("cp.async.wait_group 1;")
#define CP_WAIT0()  asm volatile("cp.async.wait_group 0;")

__device__ __forceinline__ uint32_t smem_u32(const void* p) {
    return (uint32_t)__cvta_generic_to_shared(p);
}

// ---------------- kernel 0: zero expert counters ----------------
__global__ void zero_kernel() {
    if (threadIdx.x < NEXP) g_cnt[threadIdx.x] = 0;
}

// ---------------- weight fp32 -> fp16 kernels (dst selected device-side) ----------------
__global__ void cvt_w13_kernel(const float* __restrict__ w1,
                               const float* __restrict__ w3) {
    const int n4 = (NEXP * D_MLP * D_MODEL) / 4;
    const float* src = (blockIdx.y == 0) ? w1 : w3;
    __half* dst = (blockIdx.y == 0) ? g_w1h : g_w3h;
    const float4* s4 = reinterpret_cast<const float4*>(src);
    __half2* d2 = reinterpret_cast<__half2*>(dst);
    int i = blockIdx.x * blockDim.x + threadIdx.x;
    for (; i < n4; i += gridDim.x * blockDim.x) {
        float4 v = s4[i];
        d2[2 * i + 0] = __floats2half2_rn(v.x, v.y);
        d2[2 * i + 1] = __floats2half2_rn(v.z, v.w);
    }
}

__global__ void cvt_w2_kernel(const float* __restrict__ w2) {
    const int n4 = (NEXP * D_MLP * D_MODEL) / 4;
    const float4* s4 = reinterpret_cast<const float4*>(w2);
    __half2* d2 = reinterpret_cast<__half2*>(g_w2h);
    int i = blockIdx.x * blockDim.x + threadIdx.x;
    for (; i < n4; i += gridDim.x * blockDim.x) {
        float4 v = s4[i];
        d2[2 * i + 0] = __floats2half2_rn(v.x, v.y);
        d2[2 * i + 1] = __floats2half2_rn(v.z, v.w);
    }
}

// ---------------- gating (warp per token) + x->fp16 + slot map ----------------
__global__ void gate_kernel(const float* __restrict__ x, const float* __restrict__ wg) {
    int t = blockIdx.x * 4 + (threadIdx.x >> 5);
    int lane = threadIdx.x & 31;
    if (t >= T_TOK) return;
    const float* xr = x + (size_t)t * D_MODEL;
    float acc[NEXP];
#pragma unroll
    for (int e = 0; e < NEXP; e++) acc[e] = 0.f;
    for (int d = lane; d < D_MODEL; d += 32) {
        float xv = xr[d];
        g_xh[(size_t)t * D_MODEL + d] = __float2half_rn(xv);
#pragma unroll
        for (int e = 0; e < NEXP; e++) acc[e] += xv * wg[e * D_MODEL + d];
    }
#pragma unroll
    for (int e = 0; e < NEXP; e++)
#pragma unroll
        for (int o = 16; o; o >>= 1) acc[e] += __shfl_xor_sync(0xFFFFFFFFu, acc[e], o);
    if (lane == 0) {
        int i0 = 0;
        float l0 = acc[0];
#pragma unroll
        for (int e = 1; e < NEXP; e++)
            if (acc[e] > l0) { l0 = acc[e]; i0 = e; }
        int i1 = -1;
        float l1 = -INFINITY;
#pragma unroll
        for (int e = 0; e < NEXP; e++)
            if (e != i0 && acc[e] > l1) { l1 = acc[e]; i1 = e; }
        float e1 = expf(l1 - l0);
        float s = 1.f + e1;
        float w0 = 1.f / s, w1 = e1 / s;
        int p0 = atomicAdd(&g_cnt[i0], 1);
        g_list[i0 * T_TOK + p0] = t;
        int p1 = atomicAdd(&g_cnt[i1], 1);
        g_list[i1 * T_TOK + p1] = t;
        g_slot0[t] = i0 * T_TOK + p0;
        g_slot1[t] = i1 * T_TOK + p1;
        g_cw0[t] = w0;
        g_cw1[t] = w1;
    }
}

// ---------------- grouped GEMM1: h = silu(X@W1^T) * (X@W3^T), fp16 out ----------------
// grid: (D_MLP/BN, T_TOK/BM, NEXP), block 256, dynamic smem NS1*STAGE1
__global__ void __launch_bounds__(THREADS, 2) gemm1_kernel() {
    int e = blockIdx.z, mt = blockIdx.y, nt = blockIdx.x;
    int cnt = g_cnt[e];
    if (mt * BM >= cnt) return;

    extern __shared__ __align__(128) char sm1[];
    uint32_t sbase = smem_u32(sm1);

    int tid = threadIdx.x, lane = tid & 31, warp = tid >> 5;
    int wm = warp & 3, wn = warp >> 2;       // 4 x 2 warp grid
    int g = lane >> 2, tg = lane & 3;
    int l15 = lane & 15, hi = lane >> 4;

    // ---- global->smem load setup (16B chunks, 8 per 128B row) ----
    const __half* asrc[4]; uint32_t adst[4];
#pragma unroll
    for (int i = 0; i < 4; i++) {
        int lin = i * THREADS + tid;
        int row = lin >> 3, ch = lin & 7;
        int s = mt * BM + row;
        int tok = g_list[e * T_TOK + min(s, cnt - 1)];
        asrc[i] = g_xh + (size_t)tok * D_MODEL + ch * 8;
        adst[i] = sbase + row * 128 + ((uint32_t)(ch ^ (row & 7)) << 4);
    }
    const __half* b1src[2]; const __half* b3src[2]; uint32_t bdst[2];
#pragma unroll
    for (int i = 0; i < 2; i++) {
        int lin = i * THREADS + tid;
        int row = lin >> 3, ch = lin & 7;
        size_t off = ((size_t)e * D_MLP + nt * BN + row) * D_MODEL + ch * 8;
        b1src[i] = g_w1h + off;
        b3src[i] = g_w3h + off;
        bdst[i] = sbase + A_BYTES + row * 128 + ((uint32_t)(ch ^ (row & 7)) << 4);
    }

    // ---- ldmatrix address precompute ----
    uint32_t aA[2]; int xA[2];
#pragma unroll
    for (int tm = 0; tm < 2; tm++) {
        int r = wm * 32 + tm * 16 + l15;
        aA[tm] = sbase + r * 128;
        xA[tm] = r & 7;
    }
    uint32_t aB[2]; int xB[2];
#pragma unroll
    for (int ns = 0; ns < 2; ns++) {
        int r = wn * 32 + ns * 16 + l15;
        aB[ns] = sbase + A_BYTES + r * 128;
        xB[ns] = r & 7;
    }

    float c1[2][4][4] = {}, c3[2][4][4] = {};

    const int NK = D_MODEL / BK;  // 16

    auto fill = [&](int st, int kc) {
        uint32_t so = (uint32_t)st * STAGE1;
        int ko = kc * BK;
#pragma unroll
        for (int i = 0; i < 4; i++) cp16(adst[i] + so, asrc[i] + ko);
#pragma unroll
        for (int i = 0; i < 2; i++) {
            cp16(bdst[i] + so, b1src[i] + ko);
            cp16(bdst[i] + so + B_BYTES, b3src[i] + ko);
        }
        CP_COMMIT();
    };

    fill(0, 0);
    fill(1, 1);

    for (int kt = 0; kt < NK; kt++) {
        if (kt < NK - 1) { CP_WAIT1(); } else { CP_WAIT0(); }
        __syncthreads();
        if (kt + 2 < NK) fill((kt + 2) % NS1, kt + 2);
        uint32_t so = (uint32_t)(kt % NS1) * STAGE1;
#pragma unroll
        for (int kk = 0; kk < 4; kk++) {
            uint32_t a[2][4], q1[2][4], q3[2][4];
#pragma unroll
            for (int tm = 0; tm < 2; tm++)
                ldsm4(a[tm], aA[tm] + so + ((uint32_t)((kk * 2 + hi) ^ xA[tm]) << 4));
#pragma unroll
            for (int ns = 0; ns < 2; ns++) {
                uint32_t sw = (uint32_t)((kk * 2 + hi) ^ xB[ns]) << 4;
                ldsm4(q1[ns], aB[ns] + so + sw);
                ldsm4(q3[ns], aB[ns] + so + sw + B_BYTES);
            }
#pragma unroll
            for (int tm = 0; tm < 2; tm++)
#pragma unroll
                for (int ns = 0; ns < 2; ns++) {
                    uint32_t b1a[2] = {q1[ns][0], q1[ns][2]}, b1b[2] = {q1[ns][1], q1[ns][3]};
                    uint32_t b3a[2] = {q3[ns][0], q3[ns][2]}, b3b[2] = {q3[ns][1], q3[ns][3]};
                    mma16816(c1[tm][ns * 2 + 0], a[tm], b1a);
                    mma16816(c1[tm][ns * 2 + 1], a[tm], b1b);
                    mma16816(c3[tm][ns * 2 + 0], a[tm], b3a);
                    mma16816(c3[tm][ns * 2 + 1], a[tm], b3b);
                }
        }
    }

    // epilogue: h = silu(h1) * h3 -> fp16
#pragma unroll
    for (int tm = 0; tm < 2; tm++)
#pragma unroll
        for (int pair = 0; pair < 2; pair++) {
            int s = mt * BM + wm * 32 + tm * 16 + g + pair * 8;
            if (s >= cnt) continue;
#pragma unroll
            for (int tn = 0; tn < 4; tn++) {
                float h1a = c1[tm][tn][pair * 2 + 0];
                float h1b = c1[tm][tn][pair * 2 + 1];
                float h3a = c3[tm][tn][pair * 2 + 0];
                float h3b = c3[tm][tn][pair * 2 + 1];
                float ha = h1a / (1.f + expf(-h1a)) * h3a;
                float hb = h1b / (1.f + expf(-h1b)) * h3b;
                int col = nt * BN + wn * 32 + tn * 8 + tg * 2;
                *reinterpret_cast<__half2*>(&g_h[((size_t)e * T_TOK + s) * D_MLP + col]) =
                    __floats2half2_rn(ha, hb);
            }
        }
}

// ---------------- grouped GEMM2: scr[slot] = H @ W2^T (4-stage pipeline) ----------------
// grid: (D_MODEL/BN, T_TOK/BM, NEXP), block 256, dynamic smem NS2*STAGE2
__global__ void __launch_bounds__(THREADS, 2) gemm2_kernel() {
    int e = blockIdx.z, mt = blockIdx.y, nt = blockIdx.x;
    int cnt = g_cnt[e];
    if (mt * BM >= cnt) return;

    extern __shared__ __align__(128) char sm2[];
    uint32_t sbase = smem_u32(sm2);

    int tid = threadIdx.x, lane = tid & 31, warp = tid >> 5;
    int wm = warp & 3, wn = warp >> 2;
    int g = lane >> 2, tg = lane & 3;
    int l15 = lane & 15, hi = lane >> 4;

    const __half* asrc[4]; uint32_t adst[4];
#pragma unroll
    for (int i = 0; i < 4; i++) {
        int lin = i * THREADS + tid;
        int row = lin >> 3, ch = lin & 7;
        asrc[i] = g_h + ((size_t)e * T_TOK + mt * BM + row) * D_MLP + ch * 8;
        adst[i] = sbase + row * 128 + ((uint32_t)(ch ^ (row & 7)) << 4);
    }
    const __half* bsrc[2]; uint32_t bdst[2];
#pragma unroll
    for (int i = 0; i < 2; i++) {
        int lin = i * THREADS + tid;
        int row = lin >> 3, ch = lin & 7;
        bsrc[i] = g_w2h + ((size_t)e * D_MODEL + nt * BN + row) * D_MLP + ch * 8;
        bdst[i] = sbase + A_BYTES + row * 128 + ((uint32_t)(ch ^ (row & 7)) << 4);
    }

    uint32_t aA[2]; int xA[2];
#pragma unroll
    for (int tm = 0; tm < 2; tm++) {
        int r = wm * 32 + tm * 16 + l15;
        aA[tm] = sbase + r * 128;
        xA[tm] = r & 7;
    }
    uint32_t aB[2]; int xB[2];
#pragma unroll
    for (int ns = 0; ns < 2; ns++) {
        int r = wn * 32 + ns * 16 + l15;
        aB[ns] = sbase + A_BYTES + r * 128;
        xB[ns] = r & 7;
    }

    float c[2][4][4] = {};

    const int NK = D_MLP / BK;  // 56

    auto fill = [&](int st, int kc) {
        uint32_t so = (uint32_t)st * STAGE2;
        int ko = kc * BK;
#pragma unroll
        for (int i = 0; i < 4; i++) cp16(adst[i] + so, asrc[i] + ko);
#pragma unroll
        for (int i = 0; i < 2; i++) cp16(bdst[i] + so, bsrc[i] + ko);
        CP_COMMIT();
    };

    fill(0, 0);
    fill(1, 1);
    fill(2, 2);

    for (int kt = 0; kt < NK; kt++) {
        int rem = NK - 1 - kt;
        if (rem >= 2)      { CP_WAIT2(); }
        else if (rem == 1) { CP_WAIT1(); }
        else               { CP_WAIT0(); }
        __syncthreads();
        if (kt + 3 < NK) fill((kt + 3) & 3, kt + 3);
        uint32_t so = (uint32_t)(kt & 3) * STAGE2;
#pragma unroll
        for (int kk = 0; kk < 4; kk++) {
            uint32_t a[2][4], q[2][4];
#pragma unroll
            for (int tm = 0; tm < 2; tm++)
                ldsm4(a[tm], aA[tm] + so + ((uint32_t)((kk * 2 + hi) ^ xA[tm]) << 4));
#pragma unroll
            for (int ns = 0; ns < 2; ns++)
                ldsm4(q[ns], aB[ns] + so + ((uint32_t)((kk * 2 + hi) ^ xB[ns]) << 4));
#pragma unroll
            for (int tm = 0; tm < 2; tm++)
#pragma unroll
                for (int ns = 0; ns < 2; ns++) {
                    uint32_t ba[2] = {q[ns][0], q[ns][2]}, bb[2] = {q[ns][1], q[ns][3]};
                    mma16816(c[tm][ns * 2 + 0], a[tm], ba);
                    mma16816(c[tm][ns * 2 + 1], a[tm], bb);
                }
        }
    }

    // epilogue: plain stores to per-slot scratch
#pragma unroll
    for (int tm = 0; tm < 2; tm++)
#pragma unroll
        for (int pair = 0; pair < 2; pair++) {
            int s = mt * BM + wm * 32 + tm * 16 + g + pair * 8;
            if (s >= cnt) continue;
            float* dst = g_scr + ((size_t)e * T_TOK + s) * D_MODEL;
#pragma unroll
            for (int tn = 0; tn < 4; tn++) {
                int col = nt * BN + wn * 32 + tn * 8 + tg * 2;
                float2 v = make_float2(c[tm][tn][pair * 2 + 0], c[tm][tn][pair * 2 + 1]);
                *reinterpret_cast<float2*>(dst + col) = v;
            }
        }
}

// ---------------- combine: out[t] = w0*scr[slot0] + w1*scr[slot1] ----------------
__global__ void combine_kernel(float* __restrict__ out) {
    int t = blockIdx.x;
    int d4 = threadIdx.x;
    int s0 = g_slot0[t], s1 = g_slot1[t];
    float w0 = g_cw0[t], w1 = g_cw1[t];
    const float4* a = reinterpret_cast<const float4*>(g_scr + (size_t)s0 * D_MODEL);
    const float4* b = reinterpret_cast<const float4*>(g_scr + (size_t)s1 * D_MODEL);
    float4 va = a[d4], vb = b[d4];
    float4 r;
    r.x = w0 * va.x + w1 * vb.x;
    r.y = w0 * va.y + w1 * vb.y;
    r.z = w0 * va.z + w1 * vb.z;
    r.w = w0 * va.w + w1 * vb.w;
    reinterpret_cast<float4*>(out + (size_t)t * D_MODEL)[d4] = r;
}

// ---------------- stream/event resources (host objects only; created once on the
// correctness call, BEFORE graph capture — no device memory involved) ----------------
struct MoeResources {
    cudaStream_t s1, s2;
    cudaEvent_t e0, e1, e2;
    MoeResources() {
        cudaStreamCreateWithFlags(&s1, cudaStreamNonBlocking);
        cudaStreamCreateWithFlags(&s2, cudaStreamNonBlocking);
        cudaEventCreateWithFlags(&e0, cudaEventDisableTiming);
        cudaEventCreateWithFlags(&e1, cudaEventDisableTiming);
        cudaEventCreateWithFlags(&e2, cudaEventDisableTiming);
        cudaFuncSetAttribute(gemm1_kernel, cudaFuncAttributeMaxDynamicSharedMemorySize, NS1 * STAGE1);
        cudaFuncSetAttribute(gemm2_kernel, cudaFuncAttributeMaxDynamicSharedMemorySize, NS2 * STAGE2);
    }
};

// ---------------- launch ----------------
extern "C" void kernel_launch(void* const* d_in, const int* in_sizes, int n_in,
                              void* d_out, int out_size) {
    const float* x = (const float*)d_in[0];
    const float* w_gate = (const float*)d_in[1];
    const float* w1 = (const float*)d_in[2];
    const float* w3 = (const float*)d_in[3];
    const float* w2 = (const float*)d_in[4];
    float* out = (float*)d_out;

    static MoeResources res;  // constructed on first (non-captured) call

    // fork point on the main (captured) stream
    cudaEventRecord(res.e0, 0);

    // s1: zero counters -> gating (+ x fp16 conversion)
    cudaStreamWaitEvent(res.s1, res.e0, 0);
    zero_kernel<<<1, 32, 0, res.s1>>>();
    gate_kernel<<<T_TOK / 4, 128, 0, res.s1>>>(x, w_gate);
    cudaEventRecord(res.e1, res.s1);

    // s2: W2 conversion (only needed by gemm2)
    cudaStreamWaitEvent(res.s2, res.e0, 0);
    cvt_w2_kernel<<<2048, 256, 0, res.s2>>>(w2);
    cudaEventRecord(res.e2, res.s2);

    // main: W1/W3 conversion (critical path for gemm1)
    dim3 gcvt(2048, 2);
    cvt_w13_kernel<<<gcvt, 256>>>(w1, w3);

    // join s1, then gemm1
    cudaStreamWaitEvent(0, res.e1, 0);
    dim3 g1(D_MLP / BN, T_TOK / BM, NEXP);
    gemm1_kernel<<<g1, THREADS, NS1 * STAGE1>>>();

    // join s2, then gemm2
    cudaStreamWaitEvent(0, res.e2, 0);
    dim3 g2(D_MODEL / BN, T_TOK / BM, NEXP);
    gemm2_kernel<<<g2, THREADS, NS2 * STAGE2>>>();

    // weighted combine
    combine_kernel<<<T_TOK, 256>>>(out);
}